// round 13
// baseline (speedup 1.0000x reference)
#include <cuda_runtime.h>
#include <cstdint>

#define ALPHA 0.9048374180359595f   // exp(-1/10), rounds to same f32 as JAX
#define BT 12800                     // B*T = 128*100

// Layer-1 pooled conv output, layout [sample = b*100+t][256 = c*64+y*8+x]
__device__ float g_h1[BT * 256];

// ---------------------------------------------------------------------------
// Stage 1 (reverted to round-11 form, measured ~44us; + in-kernel weight fold).
// Folded conv1(5x5,pad2)+pool4 as 8x8 stride-4 conv. 4 samples/block,
// 256 threads: thread = (sl = tid>>6, pos = tid&63 -> (py,px)), computes all
// 4 output channels (weights = one uniform float4 broadcast per tap).
// smem (q,r)-split layout: xs[sl][ic][r][row][q'] holds x col 4(q'-1)+r at
// padded row (y+2); stride-4 compute reads are bank-conflict-free.
// ---------------------------------------------------------------------------
__global__ void __launch_bounds__(256) k_stage1(const float* __restrict__ x,
                                                const float* __restrict__ w1) {
    __shared__ float xs[4][2][4][36][10];   // 11520 floats = 46 KB
    __shared__ float4 wq[128];              // [(ic*8+dy)*8+dx] -> {c0,c1,c2,c3}
    int tid = threadIdx.x;

    // fold conv1+pool weights (idempotent, L2-cached reads, ~2 entries/thread)
    float* wqf = (float*)wq;
    for (int e = tid; e < 512; e += 256) {
        int c = e & 3, tap = e >> 2;
        int dx = tap & 7, dy = (tap >> 3) & 7, ic = tap >> 6;
        int iy0 = dy > 3 ? dy - 3 : 0, iy1 = dy < 4 ? dy : 4;
        int ix0 = dx > 3 ? dx - 3 : 0, ix1 = dx < 4 ? dx : 4;
        float s = 0.f;
        for (int iy = iy0; iy <= iy1; iy++)
            for (int ix = ix0; ix <= ix1; ix++)
                s += w1[((c * 2 + ic) * 5 + iy) * 5 + ix];
        wqf[e] = s * (1.0f / 16.0f);
    }
    float* xsf = (float*)xs;
    for (int idx = tid; idx < 11520; idx += 256) xsf[idx] = 0.f;
    __syncthreads();

    // load 4 samples (8192 floats) coalesced; scatter conflict-free
    const float* xg = x + (size_t)blockIdx.x * 8192;
#pragma unroll
    for (int k = 0; k < 32; k++) {
        int idx = tid + k * 256;
        int sl = idx >> 11, rem = idx & 2047;
        int ic = rem >> 10, yy = (rem >> 5) & 31, cc = rem & 31;
        xs[sl][ic][cc & 3][yy + 2][(cc >> 2) + 1] = xg[idx];
    }
    __syncthreads();

    int sl = tid >> 6, pos = tid & 63, py = pos >> 3, px = pos & 7;
    float a0 = 0.f, a1 = 0.f, a2 = 0.f, a3 = 0.f;
#pragma unroll
    for (int ic = 0; ic < 2; ic++)
#pragma unroll
        for (int dy = 0; dy < 8; dy++) {
            int row = 4 * py + dy;
#pragma unroll
            for (int dx = 0; dx < 8; dx++) {
                int u = 4 * px + dx + 2;              // col+4 encoding
                float xv = xs[sl][ic][u & 3][row][u >> 2];
                float4 w = wq[(ic * 8 + dy) * 8 + dx];  // uniform LDS.128 bcast
                a0 = fmaf(xv, w.x, a0);
                a1 = fmaf(xv, w.y, a1);
                a2 = fmaf(xv, w.z, a2);
                a3 = fmaf(xv, w.w, a3);
            }
        }
    size_t s = (size_t)blockIdx.x * 4 + sl;
    g_h1[s * 256 +   0 + pos] = a0;
    g_h1[s * 256 +  64 + pos] = a1;
    g_h1[s * 256 + 128 + pos] = a2;
    g_h1[s * 256 + 192 + pos] = a3;
}

// ---------------------------------------------------------------------------
// Stages 2-5 fused, BITWISE conv2: per-batch temporal scan (block = one b,
// 256 threads). Layer-1 spikes are packed into 8 ballot words (word w = warp
// w's 32 neurons = channel w>>1, rows (w&1)*4..+3, bit = (y&3)*8+x). The
// folded conv2 (4x4 stride-2) becomes, per output row-segment, a 4-bit nibble
// lookup into a per-block LUT of partial sums:
//   lut[((c2*4+ic)*4+dy)*16 + nib] = sum_{dx: nib bit dx} wfold2[c2][ic][dy][dx]
// Thread tid = (o = tid>>1, q = tid&1): output o = c2*16+y2*4+x2 (warp w owns
// c2 = w), q splits input channels {2q, 2q+1}; halves combined by shfl_xor(1),
// both lanes then carry identical layer-2 LIF state (pair-duplicated ballot).
// Single barrier/iter via double-buffered ballot words.
// ---------------------------------------------------------------------------
__global__ void __launch_bounds__(256) k_scan(const float* __restrict__ w2,
                                              const float* __restrict__ lin_w,
                                              float* __restrict__ out) {
    __shared__ float lut[2048];         // 8 KB
    __shared__ float lws2[256];         // interleaved [f][o]
    __shared__ uint32_t swb[2][8];      // double-buffered layer-1 spike words
    __shared__ uint32_t sbits[100][8];  // layer-2 spike words per step
    int tid = threadIdx.x;
    int b = blockIdx.x;

    // Build conv2 nibble-LUT (8 entries/thread, once per block)
    for (int e = tid; e < 2048; e += 256) {
        int nib = e & 15, row = e >> 4;
        int dy = row & 3, ic = (row >> 2) & 3, c2 = row >> 4;
        float v = 0.f;
        for (int dx = 0; dx < 4; dx++)
            if (nib >> dx & 1) {
                int iy0 = dy > 1 ? dy - 1 : 0, iy1 = dy < 2 ? dy : 2;
                int ix0 = dx > 1 ? dx - 1 : 0, ix1 = dx < 2 ? dx : 2;
                for (int iy = iy0; iy <= iy1; iy++)
                    for (int ix = ix0; ix <= ix1; ix++)
                        v += w2[((c2 * 4 + ic) * 3 + iy) * 3 + ix];
            }
        lut[e] = v * 0.25f;
    }
    lws2[tid] = lin_w[(tid & 1) * 128 + (tid >> 1)];   // lws2[f*2+o]

    int lane = tid & 31, warp = tid >> 5;
    int q = tid & 1, o = tid >> 1;
    int c2 = o >> 4, y2 = (o >> 2) & 3, x2 = o & 3;
    const float* lrow = lut + (c2 * 4) * 64;   // base for this lane's channel

    float v1m = 0.f, v1u = 0.f, v2m = 0.f, v2u = 0.f;
    const float* hp = g_h1 + (size_t)b * 100 * 256;
    float hcur = hp[tid];
    float hnext = hp[256 + tid];
    __syncthreads();

    for (int t = 0; t < 100; t++) {
        float h = hcur;
        hcur = hnext;
        if (t < 98) hnext = hp[(t + 2) * 256 + tid];   // prefetch (L2-resident)

        // layer-1 exp_leak membrane, then LIF (membrane-subtract reset)
        v1m = ALPHA * v1m + h;
        v1u = ALPHA * v1u + v1m;
        bool s1 = (v1u >= 1.0f);
        v1u -= s1 ? 1.0f : 0.0f;
        int p = t & 1;
        uint32_t m1 = __ballot_sync(0xffffffffu, s1);
        if (lane == 0) swb[p][warp] = m1;
        __syncthreads();   // single barrier (double buffer handles WAR)

        // read the 8 spike words (broadcast LDS)
        uint32_t swv[8];
#pragma unroll
        for (int w8 = 0; w8 < 8; w8++) swv[w8] = swb[p][w8];

        // bitwise folded conv2+pool2 via nibble LUT; this lane: ic in {2q,2q+1}
        float acc = 0.f;
#pragma unroll
        for (int ri = 0; ri < 2; ri++) {
            int ic = 2 * q + ri;
#pragma unroll
            for (int dy = 0; dy < 4; dy++) {
                int r = 2 * y2 - 1 + dy;                 // input row, may clip
                uint32_t wv = swv[ic * 2 + ((r >> 2) & 1)];
                uint32_t rb = ((unsigned)r < 8u)
                                  ? ((wv >> ((r & 3) * 8)) & 0xFFu) : 0u;
                uint32_t nib = ((rb << 1) >> (2 * x2)) & 15u;  // cols 2x2-1..+2
                acc += lrow[(ic * 4 + dy) * 16 + nib];
            }
        }
        acc += __shfl_xor_sync(0xffffffffu, acc, 1);   // combine ic halves

        // layer-2 exp_leak + LIF (pair-duplicated, identical on both lanes)
        v2m = ALPHA * v2m + acc;
        v2u = ALPHA * v2u + v2m;
        bool s2 = (v2u >= 1.0f);
        v2u -= s2 ? 1.0f : 0.0f;

        uint32_t m2 = __ballot_sync(0xffffffffu, s2);  // bits pair-duplicated
        if (lane == 0) sbits[t][warp] = m2;
    }
    __syncthreads();

    // Deferred linear: out[b,t,o] = sum_f lw[o,f] * spike[t,f]
    // feature f owned by warp f>>4, even bit 2*(f&15)
    if (tid < 200) {
        int t = tid >> 1, oo = tid & 1;
        float acc = 0.f;
#pragma unroll
        for (int w8 = 0; w8 < 8; w8++) {
            uint32_t m = sbits[t][w8];
#pragma unroll
            for (int k = 0; k < 16; k++)
                if (m >> (2 * k) & 1u) acc += lws2[(w8 * 16 + k) * 2 + oo];
        }
        out[(b * 100 + t) * 2 + oo] = acc;
    }
}

// ---------------------------------------------------------------------------
extern "C" void kernel_launch(void* const* d_in, const int* in_sizes, int n_in,
                              void* d_out, int out_size) {
    // Rank-based input binding: invariant to metadata ordering AND units.
    int xi = 0;
    for (int i = 1; i < n_in; i++)
        if (in_sizes[i] > in_sizes[xi]) xi = i;

    int rest[3]; int nr = 0;
    for (int i = 0; i < n_in && nr < 3; i++)
        if (i != xi) rest[nr++] = i;
    for (int a = 0; a < 2; a++)
        for (int bq = 0; bq < 2 - a; bq++)
            if (in_sizes[rest[bq]] > in_sizes[rest[bq + 1]]) {
                int tmp = rest[bq]; rest[bq] = rest[bq + 1]; rest[bq + 1] = tmp;
            }

    const float* x  = (const float*)d_in[xi];       // [128,100,2,32,32]
    const float* w1 = (const float*)d_in[rest[0]];  // [4,2,5,5]   (200)
    const float* lw = (const float*)d_in[rest[1]];  // [2,128]     (256)
    const float* w2 = (const float*)d_in[rest[2]];  // [8,4,3,3]   (288)
    float* out = (float*)d_out;                     // [128,100,2]

    k_stage1<<<3200, 256>>>(x, w1);
    k_scan<<<128, 256>>>(w2, lw, out);
}

// round 14
// speedup vs baseline: 1.5006x; 1.5006x over previous
#include <cuda_runtime.h>
#include <cstdint>

#define ALPHA 0.9048374180359595f   // exp(-1/10), rounds to same f32 as JAX
#define BT 12800                     // B*T = 128*100

// Layer-1 pooled conv output, layout [sample = b*100+t][256 = c*64+y*8+x]
__device__ float g_h1[BT * 256];

// ---------------------------------------------------------------------------
// Stage 1 (round-11 form, best measured; in-kernel weight fold).
// Folded conv1(5x5,pad2)+pool4 as 8x8 stride-4 conv. 4 samples/block,
// 256 threads: thread = (sl = tid>>6, pos = tid&63 -> (py,px)), computes all
// 4 output channels (weights = one uniform float4 broadcast per tap).
// smem (q,r)-split layout: xs[sl][ic][r][row][q'] holds x col 4(q'-1)+r at
// padded row (y+2); stride-4 compute reads are bank-conflict-free.
// ---------------------------------------------------------------------------
__global__ void __launch_bounds__(256) k_stage1(const float* __restrict__ x,
                                                const float* __restrict__ w1) {
    __shared__ float xs[4][2][4][36][10];   // 11520 floats = 46 KB
    __shared__ float4 wq[128];              // [(ic*8+dy)*8+dx] -> {c0,c1,c2,c3}
    int tid = threadIdx.x;

    // fold conv1+pool weights (2 entries/thread, L1/L2-cached reads)
    float* wqf = (float*)wq;
    for (int e = tid; e < 512; e += 256) {
        int c = e & 3, tap = e >> 2;
        int dx = tap & 7, dy = (tap >> 3) & 7, ic = tap >> 6;
        int iy0 = dy > 3 ? dy - 3 : 0, iy1 = dy < 4 ? dy : 4;
        int ix0 = dx > 3 ? dx - 3 : 0, ix1 = dx < 4 ? dx : 4;
        float s = 0.f;
        for (int iy = iy0; iy <= iy1; iy++)
            for (int ix = ix0; ix <= ix1; ix++)
                s += w1[((c * 2 + ic) * 5 + iy) * 5 + ix];
        wqf[e] = s * (1.0f / 16.0f);
    }
    float* xsf = (float*)xs;
    for (int idx = tid; idx < 11520; idx += 256) xsf[idx] = 0.f;
    __syncthreads();

    // load 4 samples (8192 floats) coalesced; scatter conflict-free
    const float* xg = x + (size_t)blockIdx.x * 8192;
#pragma unroll
    for (int k = 0; k < 32; k++) {
        int idx = tid + k * 256;
        int sl = idx >> 11, rem = idx & 2047;
        int ic = rem >> 10, yy = (rem >> 5) & 31, cc = rem & 31;
        xs[sl][ic][cc & 3][yy + 2][(cc >> 2) + 1] = xg[idx];
    }
    __syncthreads();

    int sl = tid >> 6, pos = tid & 63, py = pos >> 3, px = pos & 7;
    float a0 = 0.f, a1 = 0.f, a2 = 0.f, a3 = 0.f;
#pragma unroll
    for (int ic = 0; ic < 2; ic++)
#pragma unroll
        for (int dy = 0; dy < 8; dy++) {
            int row = 4 * py + dy;
#pragma unroll
            for (int dx = 0; dx < 8; dx++) {
                int u = 4 * px + dx + 2;              // col+4 encoding
                float xv = xs[sl][ic][u & 3][row][u >> 2];
                float4 w = wq[(ic * 8 + dy) * 8 + dx];  // uniform LDS.128 bcast
                a0 = fmaf(xv, w.x, a0);
                a1 = fmaf(xv, w.y, a1);
                a2 = fmaf(xv, w.z, a2);
                a3 = fmaf(xv, w.w, a3);
            }
        }
    size_t s = (size_t)blockIdx.x * 4 + sl;
    g_h1[s * 256 +   0 + pos] = a0;
    g_h1[s * 256 +  64 + pos] = a1;
    g_h1[s * 256 + 128 + pos] = a2;
    g_h1[s * 256 + 192 + pos] = a3;
}

// ---------------------------------------------------------------------------
// Stages 2-5 fused, bitwise conv2 with STATIC indexing only.
// Block = one b, 256 threads. Layer-1 spikes (256 lanes) -> ballot into 8
// words (word w = neurons 32w..32w+31; bit = (y&3)*8+x). Conv lanes (tid<128,
// one output o = c2*16+y2*4+x2 each) read the 8 words into named registers
// and evaluate the folded 4x4 stride-2 conv via 4-bit nibble LUT:
//   lut[c2*272 + ((ic*4+dy)*16 + nib)] = sum_{dx in nib} wfold2[c2][ic][dy][dx]
// 272 stride => even/odd c2 in a warp hit disjoint bank halves; equal nibs
// broadcast => conv LDS is conflict-free. dy outer (runtime row/shift hoisted),
// ic inner fully unrolled => word select is a single SEL between two named
// registers. Single barrier/iter via double-buffered spike words; layer-2
// spikes ballotted to sbits; linear [2,128] deferred post-loop.
// ---------------------------------------------------------------------------
__global__ void __launch_bounds__(256) k_scan(const float* __restrict__ w2,
                                              const float* __restrict__ lin_w,
                                              float* __restrict__ out) {
    __shared__ float lut[8 * 272];      // 8704 B, padded stride
    __shared__ float lws2[256];         // interleaved [f][o]
    __shared__ uint32_t swb[2][8];      // double-buffered layer-1 spike words
    __shared__ uint32_t sbits[100][4];  // layer-2 spike words per step
    int tid = threadIdx.x;
    int b = blockIdx.x;

    // Build conv2 nibble-LUT (8 entries/thread, once per block)
    for (int e = tid; e < 2048; e += 256) {
        int c2 = e >> 8, rem = e & 255;
        int nib = rem & 15, dy = (rem >> 4) & 3, ic = rem >> 6;
        float v = 0.f;
        for (int dx = 0; dx < 4; dx++)
            if (nib >> dx & 1) {
                int iy0 = dy > 1 ? dy - 1 : 0, iy1 = dy < 2 ? dy : 2;
                int ix0 = dx > 1 ? dx - 1 : 0, ix1 = dx < 2 ? dx : 2;
                for (int iy = iy0; iy <= iy1; iy++)
                    for (int ix = ix0; ix <= ix1; ix++)
                        v += w2[((c2 * 4 + ic) * 3 + iy) * 3 + ix];
            }
        lut[c2 * 272 + rem] = v * 0.25f;
    }
    lws2[tid] = lin_w[(tid & 1) * 128 + (tid >> 1)];   // lws2[f*2+o]

    int lane = tid & 31, warp = tid >> 5;
    int c2 = tid >> 4, y2 = (tid >> 2) & 3, x2 = tid & 3;   // valid tid<128
    const float* lrow = lut + c2 * 272;
    int xsh = 2 * x2;

    float v1m = 0.f, v1u = 0.f, v2m = 0.f, v2u = 0.f;
    const float* hp = g_h1 + (size_t)b * 100 * 256;
    float hcur = hp[tid];
    float hnext = hp[256 + tid];
    __syncthreads();

    for (int t = 0; t < 100; t++) {
        float h = hcur;
        hcur = hnext;
        if (t < 98) hnext = hp[(t + 2) * 256 + tid];   // prefetch (L2-resident)

        // layer-1 exp_leak membrane, then LIF (membrane-subtract reset)
        v1m = ALPHA * v1m + h;
        v1u = ALPHA * v1u + v1m;
        bool s1 = (v1u >= 1.0f);
        v1u -= s1 ? 1.0f : 0.0f;
        int p = t & 1;
        uint32_t m1 = __ballot_sync(0xffffffffu, s1);
        if (lane == 0) swb[p][warp] = m1;
        __syncthreads();   // single barrier (double buffer handles WAR)

        if (tid < 128) {
            // named registers -> all subsequent indexing is static
            uint32_t w0 = swb[p][0], w1w = swb[p][1], w2w = swb[p][2],
                     w3 = swb[p][3], w4 = swb[p][4], w5 = swb[p][5],
                     w6 = swb[p][6], w7 = swb[p][7];
            float acc = 0.f;
#pragma unroll
            for (int dy = 0; dy < 4; dy++) {
                int r = 2 * y2 - 1 + dy;               // runtime, hoisted per dy
                bool hv = ((unsigned)r < 8u);
                bool hb = (r & 4) != 0;                // which half-word
                int rsh = (r & 3) * 8;
                // ic = 0..3 static; SEL between two named regs each
                uint32_t v0 = hb ? w1w : w0;
                uint32_t v1 = hb ? w3 : w2w;
                uint32_t v2 = hb ? w5 : w4;
                uint32_t v3 = hb ? w7 : w6;
                uint32_t b0 = hv ? ((v0 >> rsh) & 0xFFu) : 0u;
                uint32_t b1 = hv ? ((v1 >> rsh) & 0xFFu) : 0u;
                uint32_t b2 = hv ? ((v2 >> rsh) & 0xFFu) : 0u;
                uint32_t b3 = hv ? ((v3 >> rsh) & 0xFFu) : 0u;
                uint32_t n0 = ((b0 << 1) >> xsh) & 15u;
                uint32_t n1 = ((b1 << 1) >> xsh) & 15u;
                uint32_t n2 = ((b2 << 1) >> xsh) & 15u;
                uint32_t n3 = ((b3 << 1) >> xsh) & 15u;
                acc += lrow[(0 * 4 + dy) * 16 + n0];
                acc += lrow[(1 * 4 + dy) * 16 + n1];
                acc += lrow[(2 * 4 + dy) * 16 + n2];
                acc += lrow[(3 * 4 + dy) * 16 + n3];
            }

            // layer-2 exp_leak + LIF
            v2m = ALPHA * v2m + acc;
            v2u = ALPHA * v2u + v2m;
            bool s2 = (v2u >= 1.0f);
            v2u -= s2 ? 1.0f : 0.0f;

            uint32_t m2 = __ballot_sync(0xffffffffu, s2);  // warps 0-3 full
            if (lane == 0) sbits[t][warp] = m2;
        }
    }
    __syncthreads();

    // Deferred linear: out[b,t,o] = sum_f lw[o,f] * spike[t,f], f = w*32+k
    if (tid < 200) {
        int t = tid >> 1, oo = tid & 1;
        float acc = 0.f;
#pragma unroll
        for (int w8 = 0; w8 < 4; w8++) {
            uint32_t m = sbits[t][w8];
#pragma unroll
            for (int k = 0; k < 32; k++)
                if (m >> k & 1u) acc += lws2[(w8 * 32 + k) * 2 + oo];
        }
        out[(b * 100 + t) * 2 + oo] = acc;
    }
}

// ---------------------------------------------------------------------------
extern "C" void kernel_launch(void* const* d_in, const int* in_sizes, int n_in,
                              void* d_out, int out_size) {
    // Rank-based input binding: invariant to metadata ordering AND units.
    int xi = 0;
    for (int i = 1; i < n_in; i++)
        if (in_sizes[i] > in_sizes[xi]) xi = i;

    int rest[3]; int nr = 0;
    for (int i = 0; i < n_in && nr < 3; i++)
        if (i != xi) rest[nr++] = i;
    for (int a = 0; a < 2; a++)
        for (int bq = 0; bq < 2 - a; bq++)
            if (in_sizes[rest[bq]] > in_sizes[rest[bq + 1]]) {
                int tmp = rest[bq]; rest[bq] = rest[bq + 1]; rest[bq + 1] = tmp;
            }

    const float* x  = (const float*)d_in[xi];       // [128,100,2,32,32]
    const float* w1 = (const float*)d_in[rest[0]];  // [4,2,5,5]   (200)
    const float* lw = (const float*)d_in[rest[1]];  // [2,128]     (256)
    const float* w2 = (const float*)d_in[rest[2]];  // [8,4,3,3]   (288)
    float* out = (float*)d_out;                     // [128,100,2]

    k_stage1<<<3200, 256>>>(x, w1);
    k_scan<<<128, 256>>>(w2, lw, out);
}